// round 3
// baseline (speedup 1.0000x reference)
#include <cuda_runtime.h>
#include <cstdint>

#define N_NODES 50000
#define DFEAT 128
#define MAX_E 800000
#define GR 128          // rows per GEMM block
#define KC 64           // k-chunk held in smem
#define GEMM_SMEM ((GR*KC + KC*DFEAT) * 4)   // 32KB X + 32KB W = 64KB

// ---- scratch (static device globals: allocation-free) ----
__device__ float g_hs[N_NODES * DFEAT];    // raw X@W (NOT dinv-scaled)
__device__ float g_buf[N_NODES * DFEAT];   // layer-1 output / layer-2 input
__device__ float g_dinv[N_NODES];
__device__ int   g_cnt[N_NODES];
__device__ int   g_cursor[N_NODES];
__device__ int   g_csr[MAX_E];

#define FMA2(d,a,b,c) asm("fma.rn.f32x2 %0, %1, %2, %3;" : "=l"(d) : "l"(a), "l"(b), "l"(c))

// ---------------- graph build ----------------
__global__ void zero_counters() {
    int i = blockIdx.x * blockDim.x + threadIdx.x;
    if (i < N_NODES) g_cnt[i] = 0;
}

__global__ void count_deg(const int* __restrict__ dst, int E) {
    int e = blockIdx.x * blockDim.x + threadIdx.x;
    if (e < E) atomicAdd(&g_cnt[dst[e]], 1);
}

// single-block scan over 50000 counts; writes cursor=rowptr start, dinv=rsqrt(deg+1)
__global__ void scan_deg(int E) {
    __shared__ int part[1024];
    int t = threadIdx.x;
    const int C = (N_NODES + 1023) / 1024;   // 49
    int lo = t * C;
    int hi = min(lo + C, N_NODES);
    int s = 0;
    for (int i = lo; i < hi; i++) s += g_cnt[i];
    part[t] = s;
    __syncthreads();
    for (int off = 1; off < 1024; off <<= 1) {
        int v = (t >= off) ? part[t - off] : 0;
        __syncthreads();
        part[t] += v;
        __syncthreads();
    }
    int run = (t > 0) ? part[t - 1] : 0;
    for (int i = lo; i < hi; i++) {
        g_cursor[i] = run;                    // absolute fill cursor
        int c = g_cnt[i];
        g_cnt[i] = run;                       // rowptr start (reuse cnt as rowptr)
        run += c;
        g_dinv[i] = rsqrtf((float)c + 1.0f);
    }
}

__global__ void fill_csr(const int* __restrict__ src,
                         const int* __restrict__ dst, int E) {
    int e = blockIdx.x * blockDim.x + threadIdx.x;
    if (e < E) {
        int pos = atomicAdd(&g_cursor[dst[e]], 1);   // cursor pre-seeded to rowptr
        g_csr[pos] = src[e];
    }
}

// ---------------- GEMM: out = X @ W  (f32x2 packed, 128x128 tile, 8x8/thread) --------
__global__ void __launch_bounds__(256, 2)
gemm128(const float* __restrict__ X, const float* __restrict__ W,
        float* __restrict__ out, int nrows) {
    extern __shared__ float sm[];
    float* Xs = sm;                 // [GR][KC]
    float* Ws = sm + GR * KC;       // [KC][DFEAT]
    int tid = threadIdx.x;
    int row0 = blockIdx.x * GR;
    int tr = (tid >> 4) * 8;        // thread row base within tile
    int tc = (tid & 15) * 8;        // thread col base

    unsigned long long acc[8][4];
#pragma unroll
    for (int r = 0; r < 8; r++)
#pragma unroll
        for (int p = 0; p < 4; p++) acc[r][p] = 0ULL;

    for (int kc = 0; kc < DFEAT; kc += KC) {
        // X tile: 128 rows x 64 cols = 2048 float4
        for (int i = tid; i < GR * KC / 4; i += 256) {
            int r = i >> 4;                 // /(KC/4)
            int c4 = i & 15;
            float4 v = make_float4(0.f, 0.f, 0.f, 0.f);
            if (row0 + r < nrows)
                v = ((const float4*)(X + (size_t)(row0 + r) * DFEAT + kc))[c4];
            ((float4*)(Xs + r * KC))[c4] = v;
        }
        // W tile: 64 rows x 128 cols = 2048 float4
        for (int i = tid; i < KC * DFEAT / 4; i += 256) {
            int r = i >> 5;
            int c4 = i & 31;
            ((float4*)(Ws + r * DFEAT))[c4] =
                ((const float4*)(W + (size_t)(kc + r) * DFEAT))[c4];
        }
        __syncthreads();

#pragma unroll 4
        for (int k = 0; k < KC; k++) {
            const ulonglong2* wrow = (const ulonglong2*)(Ws + k * DFEAT + tc);
            ulonglong2 w01 = wrow[0];
            ulonglong2 w23 = wrow[1];
#pragma unroll
            for (int r = 0; r < 8; r++) {
                unsigned int xu = __float_as_uint(Xs[(tr + r) * KC + k]);
                unsigned long long xp;
                asm("mov.b64 %0, {%1, %1};" : "=l"(xp) : "r"(xu));
                FMA2(acc[r][0], xp, w01.x, acc[r][0]);
                FMA2(acc[r][1], xp, w01.y, acc[r][1]);
                FMA2(acc[r][2], xp, w23.x, acc[r][2]);
                FMA2(acc[r][3], xp, w23.y, acc[r][3]);
            }
        }
        __syncthreads();
    }

#pragma unroll
    for (int r = 0; r < 8; r++) {
        int row = row0 + tr + r;
        if (row < nrows) {
            float o[8];
#pragma unroll
            for (int p = 0; p < 4; p++) {
                unsigned int lo, hi;
                asm("mov.b64 {%0, %1}, %2;" : "=r"(lo), "=r"(hi) : "l"(acc[r][p]));
                o[2 * p]     = __uint_as_float(lo);
                o[2 * p + 1] = __uint_as_float(hi);
            }
            float4* dst = (float4*)(out + (size_t)row * DFEAT + tc);
            dst[0] = make_float4(o[0], o[1], o[2], o[3]);
            dst[1] = make_float4(o[4], o[5], o[6], o[7]);
        }
    }
}

// ------ aggregation: out = relu(dinv[n]*(hs[n]*dinv[n] + sum hs[s]*dinv[s]) + b) ------
__global__ void aggregate_relu(const float* __restrict__ hs,
                               const float* __restrict__ bias,
                               float* __restrict__ out) {
    int gw = (blockIdx.x * blockDim.x + threadIdx.x) >> 5;
    int lane = threadIdx.x & 31;
    if (gw >= N_NODES) return;
    const float4* hs4 = (const float4*)hs;
    float dn = g_dinv[gw];
    float4 self = hs4[(size_t)gw * 32 + lane];
    float4 acc = make_float4(self.x * dn, self.y * dn, self.z * dn, self.w * dn);
    int e0 = g_cnt[gw];
    int e1 = g_cursor[gw];            // cursor ended at rowptr[n+1]
#pragma unroll 4
    for (int e = e0; e < e1; e++) {
        int s = g_csr[e];
        float ds = g_dinv[s];
        float4 v = hs4[(size_t)s * 32 + lane];
        acc.x = fmaf(v.x, ds, acc.x);
        acc.y = fmaf(v.y, ds, acc.y);
        acc.z = fmaf(v.z, ds, acc.z);
        acc.w = fmaf(v.w, ds, acc.w);
    }
    float4 b = ((const float4*)bias)[lane];
    float4 r;
    r.x = fmaxf(fmaf(acc.x, dn, b.x), 0.f);
    r.y = fmaxf(fmaf(acc.y, dn, b.y), 0.f);
    r.z = fmaxf(fmaf(acc.z, dn, b.z), 0.f);
    r.w = fmaxf(fmaf(acc.w, dn, b.w), 0.f);
    ((float4*)out)[(size_t)gw * 32 + lane] = r;
}

// layer-2 aggregation fused with the final 128->1 projection
__global__ void aggregate_final(const float* __restrict__ hs,
                                const float* __restrict__ bias,
                                const float* __restrict__ Wl,
                                const float* __restrict__ bl,
                                float* __restrict__ out) {
    int gw = (blockIdx.x * blockDim.x + threadIdx.x) >> 5;
    int lane = threadIdx.x & 31;
    if (gw >= N_NODES) return;
    const float4* hs4 = (const float4*)hs;
    float dn = g_dinv[gw];
    float4 self = hs4[(size_t)gw * 32 + lane];
    float4 acc = make_float4(self.x * dn, self.y * dn, self.z * dn, self.w * dn);
    int e0 = g_cnt[gw];
    int e1 = g_cursor[gw];
#pragma unroll 4
    for (int e = e0; e < e1; e++) {
        int s = g_csr[e];
        float ds = g_dinv[s];
        float4 v = hs4[(size_t)s * 32 + lane];
        acc.x = fmaf(v.x, ds, acc.x);
        acc.y = fmaf(v.y, ds, acc.y);
        acc.z = fmaf(v.z, ds, acc.z);
        acc.w = fmaf(v.w, ds, acc.w);
    }
    float4 b = ((const float4*)bias)[lane];
    float4 r;
    r.x = fmaxf(fmaf(acc.x, dn, b.x), 0.f);
    r.y = fmaxf(fmaf(acc.y, dn, b.y), 0.f);
    r.z = fmaxf(fmaf(acc.z, dn, b.z), 0.f);
    r.w = fmaxf(fmaf(acc.w, dn, b.w), 0.f);
    float4 wl = ((const float4*)Wl)[lane];
    float dot = r.x * wl.x + r.y * wl.y + r.z * wl.z + r.w * wl.w;
#pragma unroll
    for (int off = 16; off; off >>= 1)
        dot += __shfl_xor_sync(0xFFFFFFFFu, dot, off);
    if (lane == 0) out[gw] = dot + bl[0];
}

// ---------------- launch ----------------
extern "C" void kernel_launch(void* const* d_in, const int* in_sizes, int n_in,
                              void* d_out, int out_size) {
    const float* x  = (const float*)d_in[0];
    const int*   ei = (const int*)d_in[1];    // int32 (JAX x64 disabled)
    const float* W1 = (const float*)d_in[2];
    const float* b1 = (const float*)d_in[3];
    const float* W2 = (const float*)d_in[4];
    const float* b2 = (const float*)d_in[5];
    const float* Wl = (const float*)d_in[6];
    const float* bl = (const float*)d_in[7];
    float* out = (float*)d_out;

    int E = in_sizes[1] / 2;
    const int* src = ei;
    const int* dst = ei + E;

    void *p_hs, *p_buf;
    cudaGetSymbolAddress(&p_hs, g_hs);
    cudaGetSymbolAddress(&p_buf, g_buf);
    float* hs  = (float*)p_hs;
    float* buf = (float*)p_buf;

    // one-time setup (runs outside capture on the correctness call; pure host-side)
    static cudaStream_t s2 = []() {
        cudaStream_t s; cudaStreamCreateWithFlags(&s, cudaStreamNonBlocking); return s;
    }();
    static cudaEvent_t evF = []() {
        cudaEvent_t e; cudaEventCreateWithFlags(&e, cudaEventDisableTiming); return e;
    }();
    static cudaEvent_t evJ = []() {
        cudaEvent_t e; cudaEventCreateWithFlags(&e, cudaEventDisableTiming); return e;
    }();
    static bool attr_ok = []() {
        cudaFuncSetAttribute(gemm128, cudaFuncAttributeMaxDynamicSharedMemorySize, GEMM_SMEM);
        return true;
    }();
    (void)attr_ok;

    int gemm_grid = (N_NODES + GR - 1) / GR;
    int agg_grid  = (N_NODES + 7) / 8;   // 8 warps / 256-thread block

    // fork: graph build on s2, GEMM1 on main stream (independent branches)
    cudaEventRecord(evF, 0);
    cudaStreamWaitEvent(s2, evF, 0);
    zero_counters<<<(N_NODES + 255) / 256, 256, 0, s2>>>();
    count_deg<<<(E + 255) / 256, 256, 0, s2>>>(dst, E);
    scan_deg<<<1, 1024, 0, s2>>>(E);
    fill_csr<<<(E + 255) / 256, 256, 0, s2>>>(src, dst, E);
    cudaEventRecord(evJ, s2);

    gemm128<<<gemm_grid, 256, GEMM_SMEM>>>(x, W1, hs, N_NODES);   // main stream

    // join
    cudaStreamWaitEvent(0, evJ, 0);
    aggregate_relu<<<agg_grid, 256>>>(hs, b1, buf);
    gemm128<<<gemm_grid, 256, GEMM_SMEM>>>(buf, W2, hs, N_NODES);
    aggregate_final<<<agg_grid, 256>>>(hs, b2, Wl, bl, out);
}

// round 5
// speedup vs baseline: 1.0051x; 1.0051x over previous
#include <cuda_runtime.h>
#include <cstdint>

#define N_NODES 50000
#define DFEAT 128
#define MAX_E 800000
#define GR 128          // rows per GEMM block
#define KC 64           // k-chunk held in smem
#define GEMM_SMEM ((GR*KC + KC*DFEAT) * 4)   // 32KB X + 32KB W = 64KB

// ---- scratch (static device globals: allocation-free) ----
__device__ float g_hs[N_NODES * DFEAT];    // (X@W) * dinv[row]
__device__ float g_buf[N_NODES * DFEAT];   // layer-1 output / layer-2 input
__device__ float g_dinv[N_NODES];
__device__ int   g_cnt[N_NODES];           // after scan: rowptr start
__device__ int   g_cursor[N_NODES];        // fill cursor; after fill: rowptr end
__device__ int   g_csr[MAX_E];

#define FMA2(d,a,b,c) asm("fma.rn.f32x2 %0, %1, %2, %3;" : "=l"(d) : "l"(a), "l"(b), "l"(c))

// ---------------- graph build ----------------
__global__ void zero_counters() {
    int i = blockIdx.x * blockDim.x + threadIdx.x;
    if (i < N_NODES) g_cnt[i] = 0;
}

__global__ void count_deg(const int* __restrict__ dst, int E) {
    int e = blockIdx.x * blockDim.x + threadIdx.x;
    if (e < E) atomicAdd(&g_cnt[dst[e]], 1);
}

// single-block scan over 50000 counts; seeds cursor=rowptr, dinv=rsqrt(deg+1)
__global__ void scan_deg(int E) {
    __shared__ int part[1024];
    int t = threadIdx.x;
    const int C = (N_NODES + 1023) / 1024;   // 49
    int lo = t * C;
    int hi = min(lo + C, N_NODES);
    int s = 0;
    for (int i = lo; i < hi; i++) s += g_cnt[i];
    part[t] = s;
    __syncthreads();
    for (int off = 1; off < 1024; off <<= 1) {
        int v = (t >= off) ? part[t - off] : 0;
        __syncthreads();
        part[t] += v;
        __syncthreads();
    }
    int run = (t > 0) ? part[t - 1] : 0;
    for (int i = lo; i < hi; i++) {
        g_cursor[i] = run;                   // absolute fill cursor
        int c = g_cnt[i];
        g_cnt[i] = run;                      // rowptr start (reuse cnt)
        run += c;
        g_dinv[i] = rsqrtf((float)c + 1.0f);
    }
}

__global__ void fill_csr(const int* __restrict__ src,
                         const int* __restrict__ dst, int E) {
    int e = blockIdx.x * blockDim.x + threadIdx.x;
    if (e < E) {
        int pos = atomicAdd(&g_cursor[dst[e]], 1);   // cursor pre-seeded to rowptr
        g_csr[pos] = src[e];
    }
}

// ------- GEMM: out[row] = (X[row] @ W) * dinv[row]  (f32x2, 128x128 tile, 8x8/thread) ---
__global__ void __launch_bounds__(256, 2)
gemm128(const float* __restrict__ X, const float* __restrict__ W,
        float* __restrict__ out, int nrows) {
    extern __shared__ float sm[];
    float* Xs = sm;                 // [GR][KC]
    float* Ws = sm + GR * KC;       // [KC][DFEAT]
    int tid = threadIdx.x;
    int row0 = blockIdx.x * GR;
    int tr = (tid >> 4) * 8;        // thread row base within tile
    int tc = (tid & 15) * 8;        // thread col base

    unsigned long long acc[8][4];
#pragma unroll
    for (int r = 0; r < 8; r++)
#pragma unroll
        for (int p = 0; p < 4; p++) acc[r][p] = 0ULL;

    for (int kc = 0; kc < DFEAT; kc += KC) {
        for (int i = tid; i < GR * KC / 4; i += 256) {
            int r = i >> 4;
            int c4 = i & 15;
            float4 v = make_float4(0.f, 0.f, 0.f, 0.f);
            if (row0 + r < nrows)
                v = ((const float4*)(X + (size_t)(row0 + r) * DFEAT + kc))[c4];
            ((float4*)(Xs + r * KC))[c4] = v;
        }
        for (int i = tid; i < KC * DFEAT / 4; i += 256) {
            int r = i >> 5;
            int c4 = i & 31;
            ((float4*)(Ws + r * DFEAT))[c4] =
                ((const float4*)(W + (size_t)(kc + r) * DFEAT))[c4];
        }
        __syncthreads();

#pragma unroll 4
        for (int k = 0; k < KC; k++) {
            const ulonglong2* wrow = (const ulonglong2*)(Ws + k * DFEAT + tc);
            ulonglong2 w01 = wrow[0];
            ulonglong2 w23 = wrow[1];
#pragma unroll
            for (int r = 0; r < 8; r++) {
                unsigned int xu = __float_as_uint(Xs[(tr + r) * KC + k]);
                unsigned long long xp;
                asm("mov.b64 %0, {%1, %1};" : "=l"(xp) : "r"(xu));
                FMA2(acc[r][0], xp, w01.x, acc[r][0]);
                FMA2(acc[r][1], xp, w01.y, acc[r][1]);
                FMA2(acc[r][2], xp, w23.x, acc[r][2]);
                FMA2(acc[r][3], xp, w23.y, acc[r][3]);
            }
        }
        __syncthreads();
    }

#pragma unroll
    for (int r = 0; r < 8; r++) {
        int row = row0 + tr + r;
        if (row < nrows) {
            float dsc = g_dinv[row];
            float o[8];
#pragma unroll
            for (int p = 0; p < 4; p++) {
                unsigned int lo, hi;
                asm("mov.b64 {%0, %1}, %2;" : "=r"(lo), "=r"(hi) : "l"(acc[r][p]));
                o[2 * p]     = __uint_as_float(lo) * dsc;
                o[2 * p + 1] = __uint_as_float(hi) * dsc;
            }
            float4* dstp = (float4*)(out + (size_t)row * DFEAT + tc);
            dstp[0] = make_float4(o[0], o[1], o[2], o[3]);
            dstp[1] = make_float4(o[4], o[5], o[6], o[7]);
        }
    }
}

// ------ aggregation: out = relu(dinv[n]*(hs[n] + sum hs[s]) + b), hs pre-scaled ------
__global__ void aggregate_relu(const float* __restrict__ hs,
                               const float* __restrict__ bias,
                               float* __restrict__ out) {
    int gw = (blockIdx.x * blockDim.x + threadIdx.x) >> 5;
    int lane = threadIdx.x & 31;
    if (gw >= N_NODES) return;
    const float4* hs4 = (const float4*)hs;
    float4 acc = hs4[(size_t)gw * 32 + lane];   // self term (already dinv[n]-scaled)
    int e0 = g_cnt[gw];
    int e1 = g_cursor[gw];
#pragma unroll 4
    for (int e = e0; e < e1; e++) {
        int s = g_csr[e];                        // broadcast load
        float4 v = hs4[(size_t)s * 32 + lane];
        acc.x += v.x; acc.y += v.y; acc.z += v.z; acc.w += v.w;
    }
    float d = g_dinv[gw];
    float4 b = ((const float4*)bias)[lane];
    float4 r;
    r.x = fmaxf(fmaf(acc.x, d, b.x), 0.f);
    r.y = fmaxf(fmaf(acc.y, d, b.y), 0.f);
    r.z = fmaxf(fmaf(acc.z, d, b.z), 0.f);
    r.w = fmaxf(fmaf(acc.w, d, b.w), 0.f);
    ((float4*)out)[(size_t)gw * 32 + lane] = r;
}

// layer-2 aggregation fused with final 128->1 projection
__global__ void aggregate_final(const float* __restrict__ hs,
                                const float* __restrict__ bias,
                                const float* __restrict__ Wl,
                                const float* __restrict__ bl,
                                float* __restrict__ out) {
    int gw = (blockIdx.x * blockDim.x + threadIdx.x) >> 5;
    int lane = threadIdx.x & 31;
    if (gw >= N_NODES) return;
    const float4* hs4 = (const float4*)hs;
    float4 acc = hs4[(size_t)gw * 32 + lane];
    int e0 = g_cnt[gw];
    int e1 = g_cursor[gw];
#pragma unroll 4
    for (int e = e0; e < e1; e++) {
        int s = g_csr[e];
        float4 v = hs4[(size_t)s * 32 + lane];
        acc.x += v.x; acc.y += v.y; acc.z += v.z; acc.w += v.w;
    }
    float d = g_dinv[gw];
    float4 b = ((const float4*)bias)[lane];
    float4 r;
    r.x = fmaxf(fmaf(acc.x, d, b.x), 0.f);
    r.y = fmaxf(fmaf(acc.y, d, b.y), 0.f);
    r.z = fmaxf(fmaf(acc.z, d, b.z), 0.f);
    r.w = fmaxf(fmaf(acc.w, d, b.w), 0.f);
    float4 wl = ((const float4*)Wl)[lane];
    float dot = r.x * wl.x + r.y * wl.y + r.z * wl.z + r.w * wl.w;
#pragma unroll
    for (int off = 16; off; off >>= 1)
        dot += __shfl_xor_sync(0xFFFFFFFFu, dot, off);
    if (lane == 0) out[gw] = dot + bl[0];
}

// ---------------- launch ----------------
extern "C" void kernel_launch(void* const* d_in, const int* in_sizes, int n_in,
                              void* d_out, int out_size) {
    const float* x  = (const float*)d_in[0];
    const int*   ei = (const int*)d_in[1];    // int32 (JAX x64 disabled)
    const float* W1 = (const float*)d_in[2];
    const float* b1 = (const float*)d_in[3];
    const float* W2 = (const float*)d_in[4];
    const float* b2 = (const float*)d_in[5];
    const float* Wl = (const float*)d_in[6];
    const float* bl = (const float*)d_in[7];
    float* out = (float*)d_out;

    int E = in_sizes[1] / 2;
    const int* src = ei;
    const int* dst = ei + E;

    void *p_hs, *p_buf;
    cudaGetSymbolAddress(&p_hs, g_hs);
    cudaGetSymbolAddress(&p_buf, g_buf);
    float* hs  = (float*)p_hs;
    float* buf = (float*)p_buf;

    static bool attr_ok = []() {
        cudaFuncSetAttribute(gemm128, cudaFuncAttributeMaxDynamicSharedMemorySize, GEMM_SMEM);
        return true;
    }();
    (void)attr_ok;

    int gemm_grid = (N_NODES + GR - 1) / GR;
    int agg_grid  = (N_NODES + 7) / 8;   // 8 warps / 256-thread block

    // serial: build -> layer1 -> layer2
    zero_counters<<<(N_NODES + 255) / 256, 256>>>();
    count_deg<<<(E + 255) / 256, 256>>>(dst, E);
    scan_deg<<<1, 1024>>>(E);
    fill_csr<<<(E + 255) / 256, 256>>>(src, dst, E);

    gemm128<<<gemm_grid, 256, GEMM_SMEM>>>(x, W1, hs, N_NODES);
    aggregate_relu<<<agg_grid, 256>>>(hs, b1, buf);          // 6th launch -> ncu target
    gemm128<<<gemm_grid, 256, GEMM_SMEM>>>(buf, W2, hs, N_NODES);
    aggregate_final<<<agg_grid, 256>>>(hs, b2, Wl, bl, out);
}